// round 15
// baseline (speedup 1.0000x reference)
#include <cuda_runtime.h>
#include <cstdint>

// ----------------------------------------------------------------------------
// Bidirectional 6-layer GRU, SEQ=512, B=10, H=256, I=128.
// 7 live scan roles (fwd L0..L5 + bwd L5); bwd L0..L4 are dead code.
// Grid = 96 CTAs = 12 clusters of 8 (6 fwd units x 2 batch-groups of 5).
// Phase 1 (R14-proven): 8 warps, register h-part weights, x-part + head-
//   issued staging in mbar-wait shadow, ONE __syncthreads/step, push-first.
// Phase 2 (NEW): role-switched clusters run a SPECIALIZED NB=1 bwd-L5 loop:
//   warp owns 4 j, 8 lanes/j split K=384 into 48-chunks, weights register-
//   resident from GMEM, x LDG'd directly from g_stage (head-issued; flag
//   saturates so poll runs once), ONE combined mbar wait per step, shfl-tree
//   reduce, owner lane pushes 4B h to 8 peers via st.async.b32.
//   NO __syncthreads in the phase-2 loop.
// ----------------------------------------------------------------------------

#define SEQ    512
#define BATCH  10
#define NTH    256

typedef unsigned long long ull;

__device__ float g_stage[5][SEQ][BATCH][128];
__device__ int   g_flag[5][2][4][8];

// smem layout
#define WS_BYTES    (3*96*32*16)              // 147456 weights ulonglong2[g][k4][j]
#define XH_OFF      WS_BYTES
#define XH_BYTES    (2*5*384*4)               // 15360 xh[2][5][384] (ph2: [2][384])
#define PARTS_OFF   (XH_OFF + XH_BYTES)
#define PARTS_BYTES (2*8*5*32*16)             // 40960 parts[2][w][b][j] float4
#define HOWN_OFF    (PARTS_OFF + PARTS_BYTES)
#define HOWN_BYTES  (5*32*4)                  // 640
#define MBAR_OFF    (HOWN_OFF + HOWN_BYTES)   // ph1: 16 mbars; ph2: 2 mbars
#define SMEM_TOTAL  (MBAR_OFF + 128)          // 204544
#define MBAR_DELTA  (MBAR_OFF - XH_OFF)

__device__ __forceinline__ int ld_acquire(const int* p) {
    int v;
    asm volatile("ld.acquire.gpu.b32 %0, [%1];" : "=r"(v) : "l"(p) : "memory");
    return v;
}
__device__ __forceinline__ void st_release(int* p, int v) {
    asm volatile("st.release.gpu.b32 [%0], %1;" :: "l"(p), "r"(v) : "memory");
}
__device__ __forceinline__ void ffma2(ull& d, ull a, ull b) {
    asm volatile("fma.rn.f32x2 %0, %1, %2, %0;" : "+l"(d) : "l"(a), "l"(b));
}
__device__ __forceinline__ void fadd2(ull& d, ull a) {
    asm volatile("add.rn.f32x2 %0, %0, %1;" : "+l"(d) : "l"(a));
}
__device__ __forceinline__ float2 u2f2(ull u) {
    float2 f;
    asm("mov.b64 {%0, %1}, %2;" : "=f"(f.x), "=f"(f.y) : "l"(u));
    return f;
}
__device__ __forceinline__ float sigmoidf_fast(float x) {
    return 1.0f / (1.0f + __expf(-x));
}
__device__ __forceinline__ float tanhf_fast(float x) {
    return fmaf(2.0f, 1.0f / (1.0f + __expf(-2.0f * x)), -1.0f);
}
__device__ __forceinline__ uint32_t smem_u32(const void* p) {
    uint32_t a;
    asm("{ .reg .u64 t; cvta.to.shared.u64 t, %1; cvt.u32.u64 %0, t; }"
        : "=r"(a) : "l"(p));
    return a;
}
__device__ __forceinline__ uint32_t mapa_u32(uint32_t laddr, uint32_t rank) {
    uint32_t r;
    asm("mapa.shared::cluster.u32 %0, %1, %2;" : "=r"(r) : "r"(laddr), "r"(rank));
    return r;
}
__device__ __forceinline__ void st_async_f4_pre(uint32_t raddr, uint32_t rmbar,
                                                float4 v) {
    asm volatile(
        "st.async.shared::cluster.mbarrier::complete_tx::bytes.v4.f32 "
        "[%0], {%2, %3, %4, %5}, [%1];"
        :: "r"(raddr), "r"(rmbar), "f"(v.x), "f"(v.y), "f"(v.z), "f"(v.w)
        : "memory");
}
__device__ __forceinline__ void st_async_b32_pre(uint32_t raddr, uint32_t rmbar,
                                                 uint32_t v) {
    asm volatile(
        "st.async.shared::cluster.mbarrier::complete_tx::bytes.b32 "
        "[%0], %2, [%1];"
        :: "r"(raddr), "r"(rmbar), "r"(v)
        : "memory");
}
__device__ __forceinline__ void mbar_init(uint32_t mbar, uint32_t cnt) {
    asm volatile("mbarrier.init.shared.b64 [%0], %1;" :: "r"(mbar), "r"(cnt) : "memory");
}
__device__ __forceinline__ void mbar_inval(uint32_t mbar) {
    asm volatile("mbarrier.inval.shared.b64 [%0];" :: "r"(mbar) : "memory");
}
__device__ __forceinline__ void mbar_expect_tx(uint32_t mbar, uint32_t bytes) {
    asm volatile("mbarrier.arrive.expect_tx.shared.b64 _, [%0], %1;"
                 :: "r"(mbar), "r"(bytes) : "memory");
}
__device__ __forceinline__ void mbar_wait(uint32_t mbar, uint32_t parity) {
    asm volatile(
        "{\n\t.reg .pred P;\n\t"
        "LWAIT_%=:\n\t"
        "mbarrier.try_wait.parity.acquire.cluster.shared::cta.b64 P, [%0], %1, 0x989680;\n\t"
        "@!P bra LWAIT_%=;\n\t}"
        :: "r"(mbar), "r"(parity) : "memory");
}
#define CLUSTER_SYNC() do { \
    asm volatile("barrier.cluster.arrive.aligned;" ::: "memory"); \
    asm volatile("barrier.cluster.wait.aligned;"   ::: "memory"); \
} while (0)
#define BAR_STAGE() asm volatile("bar.sync 1, 96;"  ::: "memory")
#define BAR_RED()   asm volatile("bar.sync 4, 160;" ::: "memory")

// -------- weights -> smem: ws4[g][k4][j] (phase-1 only) --------------------
__device__ __forceinline__ void load_weights(
    char* smem, int tid, int layer, int dir, int j0,
    const float* __restrict__ w_ih_l0,
    const float* __restrict__ w_ih_rest,
    const float* __restrict__ w_hh)
{
    const float* Whh = w_hh + (size_t)(layer * 2 + dir) * 768 * 256;
    const float* Wih;
    int pitch;
    if (layer == 0) { Wih = w_ih_l0 + (size_t)dir * 768 * 128; pitch = 128; }
    else            { Wih = w_ih_rest + (size_t)((layer - 1) * 2 + dir) * 768 * 512; pitch = 512; }

    for (int idx = tid; idx < 3 * 96 * 32; idx += NTH) {
        int j  = idx & 31;
        int k4 = (idx >> 5) % 96;
        int g  = idx / (96 * 32);
        int row = g * 256 + j0 + j;
        int k   = k4 * 4;
        const float* src = (k < 128) ? (Wih + (size_t)row * pitch + k)
                                     : (Whh + (size_t)row * 256 + (k - 128));
        ((float4*)smem)[idx] = *(const float4*)src;
    }
}

// ============================= phase-1 scan loop ============================
// MODE: 0 = fwd hidden layer (write g_stage), 1 = fwd L5 (out left).
template<int NB, int MODE>
__device__ __forceinline__ void scan_loop(
    const float* __restrict__ x, float* __restrict__ out,
    char* smem, uint32_t smem_base,
    int u, int bg, int boff, int js, int tid)
{
    ulonglong2* ws4   = (ulonglong2*)smem;
    float*      xh    = (float*)(smem + XH_OFF);
    float4*     parts = (float4*)(smem + PARTS_OFF);   // [2][8][5][32]
    float*      hown  = (float*)(smem + HOWN_OFF);
    float4*     hown4 = (float4*)(smem + HOWN_OFF);
    const uint32_t mbar_base = smem_base + MBAR_OFF;
    const int j0 = js * 32;
    const uint32_t exp_tx = NB * 128;
    const int src_u = u - 1;

    uint32_t rxh[8];
    #pragma unroll
    for (int pe = 0; pe < 8; ++pe)
        rxh[pe] = mapa_u32(smem_base + XH_OFF, (uint32_t)pe);

    // zero h-section of buffer 0
    for (int t = tid; t < NB * 64; t += NTH) {
        int b = t >> 6, q = t & 63;
        *(float4*)&xh[b * 384 + 128 + q * 4] = make_float4(0.f, 0.f, 0.f, 0.f);
    }
    if (tid < 16) {
        mbar_init(mbar_base + tid * 8, 1);
        mbar_expect_tx(mbar_base + tid * 8, exp_tx);
    }
    __syncthreads();
    CLUSTER_SYNC();

    const int w  = tid >> 5;       // warp 0..7
    const int jl = tid & 31;
    const int xk4s = w * 4;        // x-part: 4 k4 x 3 gates (SMEM weights)
    const int hk4s = 32 + w * 8;   // h-part: 8 k4 x 3 gates (REG weights)
    const uint32_t my_mb0 = mbar_base + (uint32_t)(w * 8);
    const int t0 = tid - 160;      // staging index (warps 5-7)

    ulonglong2 whr[8], whz[8], whn[8];
    #pragma unroll
    for (int t = 0; t < 8; ++t) {
        whr[t] = ws4[(hk4s + t) * 32 + jl];
        whz[t] = ws4[(96 + hk4s + t) * 32 + jl];
        whn[t] = ws4[(192 + hk4s + t) * 32 + jl];
    }

    // prologue: stage x(0) into buffer 0 (warps 5-7)
    if (tid >= 160) {
        if (MODE == 0 && u == 0) {
            const float* src = x + ((size_t)(bg * 5 + boff)) * 128;
            for (int t = t0; t < NB * 32; t += 96) {
                int b = t >> 5, q = t & 31;
                *(float4*)&xh[b * 384 + q * 4] = *(const float4*)&src[b * 128 + q * 4];
            }
        } else {
            if (tid >= 224 && tid < 228) {
                const int* fp = &g_flag[src_u][bg][tid - 224][0];
                while (ld_acquire(fp) < 1) __nanosleep(128);
            }
            BAR_STAGE();
            const float* src = &g_stage[src_u][0][bg * 5 + boff][0];
            for (int t = t0; t < NB * 32; t += 96) {
                int b = t >> 5, q = t & 31;
                *(float4*)&xh[b * 384 + q * 4] = *(const float4*)&src[b * 128 + q * 4];
            }
        }
    }
    __syncthreads();

    uint32_t pha[2] = {0, 0};

    for (int s = 0; s < SEQ; ++s) {
        const int p = s & 1;
        const ulonglong2* X = (const ulonglong2*)(xh + p * 1920);
        float4* pb = parts + p * 1280;
        const bool do_stage = (tid >= 160) && (s + 1 < SEQ);

        // HEAD staging: poll flag + issue x(s+1) loads into registers
        float4 sx0, sx1;
        if (do_stage) {
            if (MODE == 0 && u == 0) {
                const float* src = x + ((size_t)(s + 1) * BATCH + bg * 5 + boff) * 128;
                if (t0 < NB * 32) {
                    int b = t0 >> 5, q = t0 & 31;
                    sx0 = *(const float4*)&src[b * 128 + q * 4];
                }
                if (t0 + 96 < NB * 32) {
                    int t = t0 + 96, b = t >> 5, q = t & 31;
                    sx1 = *(const float4*)&src[b * 128 + q * 4];
                }
            } else {
                if (tid >= 224 && tid < 228) {
                    const int* fp = &g_flag[src_u][bg][tid - 224][0];
                    while (ld_acquire(fp) < s + 2) __nanosleep(64);
                }
                BAR_STAGE();
                const float* src = &g_stage[src_u][s + 1][bg * 5 + boff][0];
                if (t0 < NB * 32) {
                    int b = t0 >> 5, q = t0 & 31;
                    sx0 = *(const float4*)&src[b * 128 + q * 4];
                }
                if (t0 + 96 < NB * 32) {
                    int t = t0 + 96, b = t >> 5, q = t & 31;
                    sx1 = *(const float4*)&src[b * 128 + q * 4];
                }
            }
        }

        // x-part (no h dependency)
        ull ar[NB], az[NB], anx[NB], anh[NB];
        #pragma unroll
        for (int i = 0; i < NB; ++i) { ar[i] = 0; az[i] = 0; anx[i] = 0; anh[i] = 0; }

        #pragma unroll
        for (int t = 0; t < 4; ++t) {
            int k4 = xk4s + t;
            ulonglong2 wr = ws4[k4 * 32 + jl];
            ulonglong2 wz = ws4[(96 + k4) * 32 + jl];
            ulonglong2 wn = ws4[(192 + k4) * 32 + jl];
            #pragma unroll
            for (int i = 0; i < NB; ++i) {
                ulonglong2 xv = X[i * 96 + k4];
                ffma2(ar[i],  wr.x, xv.x); ffma2(ar[i],  wr.y, xv.y);
                ffma2(az[i],  wz.x, xv.x); ffma2(az[i],  wz.y, xv.y);
                ffma2(anx[i], wn.x, xv.x); ffma2(anx[i], wn.y, xv.y);
            }
        }

        if (s > 0) {
            uint32_t mb = my_mb0 + (uint32_t)(p * 64);
            mbar_wait(mb, pha[p]);
            pha[p] ^= 1;
            if (jl == 0 && s + 2 < SEQ) mbar_expect_tx(mb, exp_tx);
        }

        // h-part: register weights
        #pragma unroll
        for (int t = 0; t < 8; ++t) {
            int k4 = hk4s + t;
            #pragma unroll
            for (int i = 0; i < NB; ++i) {
                ulonglong2 xv = X[i * 96 + k4];
                ffma2(ar[i],  whr[t].x, xv.x); ffma2(ar[i],  whr[t].y, xv.y);
                ffma2(az[i],  whz[t].x, xv.x); ffma2(az[i],  whz[t].y, xv.y);
                ffma2(anh[i], whn[t].x, xv.x); ffma2(anh[i], whn[t].y, xv.y);
            }
        }

        #pragma unroll
        for (int i = 0; i < NB; ++i) {
            float2 fr = u2f2(ar[i]),  fz = u2f2(az[i]);
            float2 fx = u2f2(anx[i]), fh = u2f2(anh[i]);
            pb[(w * NB + i) * 32 + jl] =
                make_float4(fr.x + fr.y, fz.x + fz.y, fx.x + fx.y, fh.x + fh.y);
        }

        if (do_stage) {
            float* dst = xh + (p ^ 1) * 1920;
            if (t0 < NB * 32) {
                int b = t0 >> 5, q = t0 & 31;
                *(float4*)&dst[b * 384 + q * 4] = sx0;
            }
            if (t0 + 96 < NB * 32) {
                int t = t0 + 96, b = t >> 5, q = t & 31;
                *(float4*)&dst[b * 384 + q * 4] = sx1;
            }
        }
        __syncthreads();   // THE step barrier

        if (tid < NB * 32) {
            int b = tid >> 5, j = tid & 31;
            const ulonglong2* pr = (const ulonglong2*)pb;
            ulonglong2 q0 = pr[b * 32 + j];
            ull a01 = q0.x, a23 = q0.y;
            #pragma unroll
            for (int ww = 1; ww < 8; ++ww) {
                ulonglong2 q = pr[(ww * NB + b) * 32 + j];
                fadd2(a01, q.x); fadd2(a23, q.y);
            }
            float2 f01 = u2f2(a01), f23 = u2f2(a23);
            float r = sigmoidf_fast(f01.x);
            float z = sigmoidf_fast(f01.y);
            float n = tanhf_fast(f23.x + r * f23.y);
            float hp = xh[p * 1920 + b * 384 + 128 + j0 + j];
            float h  = fmaf(z, hp - n, n);
            hown[b * 32 + j] = h;
            __syncwarp();
            if ((j & 3) == 0 && s + 1 < SEQ) {
                float4 v = hown4[b * 8 + (j >> 2)];
                uint32_t off  = (uint32_t)(((p ^ 1) * 1920 + b * 384 + 128 + j0 + j) * 4);
                uint32_t moff = (uint32_t)(MBAR_DELTA + (p ^ 1) * 64 + js * 8);
                #pragma unroll
                for (int pe = 0; pe < 8; ++pe)
                    st_async_f4_pre(rxh[pe] + off, rxh[pe] + moff, v);
            }
            int bglob = bg * 5 + boff + b;
            if (MODE == 1)   out[((size_t)s * BATCH + bglob) * 512 + j0 + j] = h;
            else if (js < 4) g_stage[u][s][bglob][j0 + j] = h;
        }
        if (MODE == 0 && tid < 160) {
            BAR_RED();
            if (js < 4 && tid == 0) {
                __threadfence();
                st_release(&g_flag[u][bg][js][0], s + 1);
            }
        }
    }
}

// ====================== phase-2 specialized bwd-L5 loop =====================
// One batch per cluster. Warp owns 4 j; 8 lanes per j split K=384 into
// 48-chunks. Register weights from GMEM. No __syncthreads in the loop.
__device__ __forceinline__ void bwd_loop(
    float* __restrict__ out, char* smem, uint32_t smem_base,
    int bg, int b, int js, int tid,
    const float* __restrict__ w_ih_rest,
    const float* __restrict__ w_hh)
{
    float* xh = (float*)(smem + XH_OFF);     // [2][384] (x128 | h256)
    const uint32_t mbar_base = smem_base + MBAR_OFF;
    const int j0 = js * 32;

    uint32_t rxh[8];
    #pragma unroll
    for (int pe = 0; pe < 8; ++pe)
        rxh[pe] = mapa_u32(smem_base + XH_OFF, (uint32_t)pe);

    // zero h of buffer 0; init 2 mbars (count 1, expect 8 CTAs x 32 j x 4B)
    if (tid < 256) xh[128 + tid] = 0.0f;
    if (tid == 0) {
        mbar_init(mbar_base, 1);
        mbar_expect_tx(mbar_base, 1024);
        mbar_init(mbar_base + 8, 1);
        mbar_expect_tx(mbar_base + 8, 1024);
    }
    __syncthreads();
    CLUSTER_SYNC();

    const int w   = tid >> 5;
    const int jl  = tid & 31;
    const int grp = jl >> 3;          // j within warp's 4
    const int sub = jl & 7;           // k-chunk index
    const int jj  = w * 4 + grp;      // 0..31 within CTA
    const int k0  = sub * 48;
    const int nx4 = (k0 < 128) ? (((128 - k0) < 48 ? (128 - k0) : 48) >> 2) : 0;

    // weights -> registers (L5 bwd: w_ih_rest idx 9 pitch 512; w_hh idx 11)
    const float* Wih = w_ih_rest + (size_t)9 * 768 * 512;
    const float* Whh = w_hh + (size_t)11 * 768 * 256;
    ulonglong2 wr[12], wz[12], wn[12];
    {
        int row = j0 + jj;
        #pragma unroll
        for (int i = 0; i < 12; ++i) {
            int k = k0 + 4 * i;
            if (k < 128) {
                wr[i] = *(const ulonglong2*)&Wih[(size_t)(row)       * 512 + k];
                wz[i] = *(const ulonglong2*)&Wih[(size_t)(256 + row) * 512 + k];
                wn[i] = *(const ulonglong2*)&Wih[(size_t)(512 + row) * 512 + k];
            } else {
                wr[i] = *(const ulonglong2*)&Whh[(size_t)(row)       * 256 + (k - 128)];
                wz[i] = *(const ulonglong2*)&Whh[(size_t)(256 + row) * 256 + (k - 128)];
                wn[i] = *(const ulonglong2*)&Whh[(size_t)(512 + row) * 256 + (k - 128)];
            }
        }
    }

    uint32_t pha[2] = {0, 0};
    bool fdone = false;

    for (int s = 0; s < SEQ; ++s) {
        const int p  = s & 1;
        const int ss = SEQ - 1 - s;

        // head: poll (only until flag saturates at 512) + issue x LDGs
        ulonglong2 xv[12];
        if (nx4 > 0) {
            if (!fdone) {
                int need = SEQ - s;
                int f0 = k0 >> 5;
                int f1 = (k0 + nx4 * 4 - 1) >> 5;
                int v0 = ld_acquire(&g_flag[4][bg][f0][0]);
                while (v0 < need) { __nanosleep(64); v0 = ld_acquire(&g_flag[4][bg][f0][0]); }
                int v1 = ld_acquire(&g_flag[4][bg][f1][0]);
                while (v1 < need) { __nanosleep(64); v1 = ld_acquire(&g_flag[4][bg][f1][0]); }
                if (v0 >= SEQ && v1 >= SEQ) fdone = true;
            }
            const float* xsrc = &g_stage[4][ss][b][0];
            #pragma unroll
            for (int i = 0; i < 12; ++i)
                if (i < nx4) xv[i] = *(const ulonglong2*)&xsrc[k0 + 4 * i];
        }

        // wait for h(s-1) from all 8 peers (one combined mbar)
        if (s > 0) {
            uint32_t mb = mbar_base + (uint32_t)(p * 8);
            mbar_wait(mb, pha[p]);
            pha[p] ^= 1;
            if (tid == 0 && s + 2 < SEQ) mbar_expect_tx(mb, 1024);
        }

        // per-lane GEMV over its 48-chunk (x from regs, h via LDS)
        ull ar = 0, az = 0, anx = 0, anh = 0;
        const float* H = &xh[p * 384];
        #pragma unroll
        for (int i = 0; i < 12; ++i) {
            int k = k0 + 4 * i;
            ulonglong2 v;
            if (i < nx4) v = xv[i];
            else         v = *(const ulonglong2*)&H[k];   // k>=128: h section
            ffma2(ar, wr[i].x, v.x); ffma2(ar, wr[i].y, v.y);
            ffma2(az, wz[i].x, v.x); ffma2(az, wz[i].y, v.y);
            if (i < nx4) { ffma2(anx, wn[i].x, v.x); ffma2(anx, wn[i].y, v.y); }
            else         { ffma2(anh, wn[i].x, v.x); ffma2(anh, wn[i].y, v.y); }
        }
        float2 t;
        t = u2f2(ar);  float sr  = t.x + t.y;
        t = u2f2(az);  float sz  = t.x + t.y;
        t = u2f2(anx); float snx = t.x + t.y;
        t = u2f2(anh); float snh = t.x + t.y;

        // shfl tree reduce within 8-lane groups
        #pragma unroll
        for (int d = 4; d > 0; d >>= 1) {
            sr  += __shfl_xor_sync(0xffffffffu, sr,  d);
            sz  += __shfl_xor_sync(0xffffffffu, sz,  d);
            snx += __shfl_xor_sync(0xffffffffu, snx, d);
            snh += __shfl_xor_sync(0xffffffffu, snh, d);
        }

        if (sub == 0) {
            float r = sigmoidf_fast(sr);
            float z = sigmoidf_fast(sz);
            float n = tanhf_fast(snx + r * snh);
            float hp = xh[p * 384 + 128 + j0 + jj];
            float h  = fmaf(z, hp - n, n);
            out[((size_t)s * BATCH + b) * 512 + 256 + j0 + jj] = h;
            if (s + 1 < SEQ) {
                uint32_t off  = (uint32_t)(((p ^ 1) * 384 + 128 + j0 + jj) * 4);
                uint32_t moff = (uint32_t)(MBAR_DELTA + (p ^ 1) * 8);
                uint32_t hv = __float_as_uint(h);
                #pragma unroll
                for (int pe = 0; pe < 8; ++pe)
                    st_async_b32_pre(rxh[pe] + off, rxh[pe] + moff, hv);
            }
        }
    }
}

// ================================ kernel ====================================
extern "C" __global__ void __launch_bounds__(NTH, 1) __cluster_dims__(8, 1, 1)
gru_persistent_kernel(const float* __restrict__ x,
                      const float* __restrict__ w_ih_l0,
                      const float* __restrict__ w_ih_rest,
                      const float* __restrict__ w_hh,
                      float* __restrict__ out)
{
    extern __shared__ char smem[];
    const uint32_t smem_base = smem_u32(smem);
    const int cta = blockIdx.x;
    const int tid = threadIdx.x;

    const int u  = cta >> 4;          // fwd unit 0..5
    const int bg = (cta >> 3) & 1;    // batch group
    const int js = cta & 7;           // cluster rank / hidden slice
    const int j0 = js * 32;

    // -------- phase 1: forward units --------
    load_weights(smem, tid, u, 0, j0, w_ih_l0, w_ih_rest, w_hh);
    __syncthreads();

    if (u < 5) scan_loop<5, 0>(x, out, smem, smem_base, u, bg, 0, js, tid);
    else       scan_loop<5, 1>(x, out, smem, smem_base, u, bg, 0, js, tid);

    // -------- phase 2: role switch — fwd unit k (k<5) becomes bwd-L5 cluster
    //          for batch bg*5+k, using the specialized NB=1 loop.
    if (u < 5) {
        __syncthreads();   // all warps past phase-1 reads of xh/mbars
        if (tid < 16)      // phase-1 mbarriers quiescent (re-arm was guarded)
            mbar_inval(smem_base + MBAR_OFF + tid * 8);
        __syncthreads();
        bwd_loop(out, smem, smem_base, bg, bg * 5 + u, js, tid, w_ih_rest, w_hh);
    }

    CLUSTER_SYNC();
}

extern "C" __global__ void zero_flags_kernel() {
    int t = threadIdx.x;
    if (t < 5 * 2 * 4 * 8) ((int*)g_flag)[t] = 0;
}

extern "C" void kernel_launch(void* const* d_in, const int* in_sizes, int n_in,
                              void* d_out, int out_size) {
    const float* x         = (const float*)d_in[0];
    const float* w_ih_l0   = (const float*)d_in[1];
    const float* w_ih_rest = (const float*)d_in[2];
    const float* w_hh      = (const float*)d_in[3];
    float* out = (float*)d_out;

    cudaFuncSetAttribute(gru_persistent_kernel,
                         cudaFuncAttributeMaxDynamicSharedMemorySize, SMEM_TOTAL);

    zero_flags_kernel<<<1, 320>>>();
    gru_persistent_kernel<<<96, NTH, SMEM_TOTAL>>>(x, w_ih_l0, w_ih_rest, w_hh, out);
}